// round 13
// baseline (speedup 1.0000x reference)
#include <cuda_runtime.h>
#include <cuda_fp16.h>
#include <cstdint>

// ---------------------------------------------------------------------------
// APUNet as one GEMM: D[o,s] = sum_i G[o,i] * Xs[s,i] ; out = D + x
//   o = c*256 + hp*16 + wp (M=8192), s = n*64 + k*8 + j (N=1024), K=8192
// fp16 mma.sync m16n8k16, BM=128 BN=256 BK=64, warps 2(M)x4(N) 64x64,
// KSPLIT=4 + red.global.add epilogue (out pre-initialized with residual).
// NEW: explicit software pipelining of ldmatrix fragments (volatile asm is
// emitted in source order, so the source order IS the schedule): A frags
// double-buffered across i, B frags double-buffered across ks. Hides the
// LDSM latency that held the tensor pipe at ~53%.
// ---------------------------------------------------------------------------

#define MDIM 8192
#define NDIM 1024
#define KDIM 8192
#define BM 128
#define BN 256
#define BK 64
#define KSPLIT 4
#define KGRAN (KDIM / KSPLIT)   // 2048
#define NCHUNK (KGRAN / BK)     // 32
#define PITCH 72                // fp16 units; 144B rows -> ldmatrix conflict-free
#define ASTAGE (BM * PITCH)     // 9216 fp16 (18 KB)
#define BSTAGE (BN * PITCH)     // 18432 fp16 (36 KB)
#define SMEM_BYTES ((2 * ASTAGE + 3 * BSTAGE) * 2)   // 147456

__device__ __half g_Xs[(size_t)NDIM * KDIM];   // 16 MB: im2col(x) in fp16

__device__ __forceinline__ uint32_t smem_u32(const void* p) {
    uint32_t a;
    asm("{ .reg .u64 t; cvta.to.shared.u64 t, %1; cvt.u32.u64 %0, t; }" : "=r"(a) : "l"(p));
    return a;
}
#define LDSM_X4(r0, r1, r2, r3, addr) \
    asm volatile("ldmatrix.sync.aligned.m8n8.x4.shared.b16 {%0,%1,%2,%3}, [%4];" \
                 : "=r"(r0), "=r"(r1), "=r"(r2), "=r"(r3) : "r"(addr))
#define MMA16816(d, a, b) \
    asm volatile("mma.sync.aligned.m16n8k16.row.col.f32.f16.f16.f32 " \
                 "{%0,%1,%2,%3}, {%4,%5,%6,%7}, {%8,%9}, {%0,%1,%2,%3};" \
                 : "+f"((d)[0]), "+f"((d)[1]), "+f"((d)[2]), "+f"((d)[3]) \
                 : "r"((a)[0]), "r"((a)[1]), "r"((a)[2]), "r"((a)[3]), \
                   "r"((b)[0]), "r"((b)[1]))

// ---------------------------------------------------------------------------
// im2col + residual init: Xs[s][i] = fp16(x), out = x  (128-bit IO throughout)
// ---------------------------------------------------------------------------
__global__ void __launch_bounds__(256) im2col_kernel(const float* __restrict__ x,
                                                     float* __restrict__ out) {
    int b = blockIdx.x;                 // (n, c, hp)
    int hp = b & 15, c = (b >> 4) & 31, n = b >> 9;
    __shared__ float tile[1024];        // [k(8)][w(128)]
    size_t base = ((size_t)((n * 32 + c) * 128 + hp * 8)) * 128;
    int t = threadIdx.x;
    {
        float4 v = *(const float4*)(x + base + t * 4);
        *(float4*)(out + base + t * 4) = v;   // residual pre-init
        *(float4*)(tile + t * 4) = v;
    }
    __syncthreads();
    int wp = t & 15;
    int ibase = c * 256 + hp * 16 + wp;
#pragma unroll
    for (int r = 0; r < 4; r++) {
        int sl = (t >> 4) + r * 16;     // 0..63 = k*8+j
        int k = sl >> 3, j = sl & 7;
        g_Xs[(size_t)(n * 64 + sl) * KDIM + ibase] =
            __float2half_rn(tile[k * 128 + wp * 8 + j]);
    }
}

// ---------------------------------------------------------------------------
// GEMM: grid (4 n, 64 m, 4 kq), 256 threads, warps 2(M) x 4(N), tile 64x64
// ---------------------------------------------------------------------------
__global__ void __launch_bounds__(256, 1) gemm_kernel(
    const float* __restrict__ G, float* __restrict__ out) {
    extern __shared__ __half sm[];
    __half* smA = sm;                    // 2 stages (reg double-buffer feed)
    __half* smB = sm + 2 * ASTAGE;       // 3 stages (cp.async)

    int t = threadIdx.x, lane = t & 31, wid = t >> 5;
    int wm = wid >> 2, wn = wid & 3;
    int m0 = blockIdx.y * BM, n0 = blockIdx.x * BN;
    int k0 = blockIdx.z * KGRAN;
    const float* gbase = G + (size_t)m0 * KDIM + k0;
    const __half* bbase = g_Xs + (size_t)n0 * KDIM + k0;

    float acc[4][8][4];
#pragma unroll
    for (int i = 0; i < 4; i++)
#pragma unroll
        for (int j = 0; j < 8; j++)
#pragma unroll
            for (int r = 0; r < 4; r++) acc[i][j][r] = 0.f;

    // ldmatrix base byte-addresses (stage 0, ks 0)
    uint32_t ldsmA = smem_u32(smA) +
        ((wm * 64 + (lane & 15)) * PITCH + (lane >> 4) * 8) * 2;
    uint32_t ldsmB = smem_u32(smB) +
        ((wn * 64 + (lane & 7) + ((lane >> 4) & 1) * 8) * PITCH + ((lane >> 3) & 1) * 8) * 2;

    // A loader: streaming fp32 LDG -> cvt fp16 -> STS.128
    float4 areg[4][2];

    auto ldgA = [&](int c) {
#pragma unroll
        for (int r = 0; r < 4; r++) {
            int v2 = t + r * 256;
            const float4* src = (const float4*)(gbase + (size_t)(v2 >> 3) * KDIM + c * BK + (v2 & 7) * 8);
            areg[r][0] = __ldcs(src);
            areg[r][1] = __ldcs(src + 1);
        }
    };
    auto stsA = [&](int buf) {
#pragma unroll
        for (int r = 0; r < 4; r++) {
            int v2 = t + r * 256;
            __half2 h0 = __floats2half2_rn(areg[r][0].x, areg[r][0].y);
            __half2 h1 = __floats2half2_rn(areg[r][0].z, areg[r][0].w);
            __half2 h2 = __floats2half2_rn(areg[r][1].x, areg[r][1].y);
            __half2 h3 = __floats2half2_rn(areg[r][1].z, areg[r][1].w);
            uint32_t dst = smem_u32(smA + buf * ASTAGE + (v2 >> 3) * PITCH + (v2 & 7) * 8);
            asm volatile("st.shared.v4.b32 [%0], {%1,%2,%3,%4};"
                         :: "r"(dst),
                            "r"(*(uint32_t*)&h0), "r"(*(uint32_t*)&h1),
                            "r"(*(uint32_t*)&h2), "r"(*(uint32_t*)&h3) : "memory");
        }
    };
    auto cpB = [&](int c) {
        __half* base = smB + (c % 3) * BSTAGE;
#pragma unroll
        for (int r = 0; r < 8; r++) {
            int v = t + r * 256;        // 2048: row = v>>3, c4 = v&7
            uint32_t dst = smem_u32(base + (v >> 3) * PITCH + (v & 7) * 8);
            const __half* src = bbase + (size_t)(v >> 3) * KDIM + c * BK + (v & 7) * 8;
            asm volatile("cp.async.cg.shared.global [%0], [%1], 16;" :: "r"(dst), "l"(src) : "memory");
        }
    };

    // prologue
    cpB(0); asm volatile("cp.async.commit_group;" ::: "memory");
    cpB(1); asm volatile("cp.async.commit_group;" ::: "memory");
    ldgA(0); stsA(0);
    ldgA(1);

    uint32_t aa[2][4];       // A fragments, double-buffered across i
    uint32_t bb[2][8][2];    // B fragments, double-buffered across ks

#pragma unroll 1
    for (int c = 0; c < NCHUNK; c++) {
        asm volatile("cp.async.wait_group 1;" ::: "memory");
        __syncthreads();
        if (c + 2 < NCHUNK) cpB(c + 2);
        asm volatile("cp.async.commit_group;" ::: "memory");
        if (c + 1 < NCHUNK) stsA((c + 1) & 1);
        if (c + 2 < NCHUNK) ldgA(c + 2);

        uint32_t aAddr = ldsmA + (c & 1) * (ASTAGE * 2);
        uint32_t bAddr = ldsmB + (c % 3) * (BSTAGE * 2);

        // chunk prologue: B(ks0) and A(ks0, i0)
#pragma unroll
        for (int j2 = 0; j2 < 4; j2++)
            LDSM_X4(bb[0][j2 * 2][0], bb[0][j2 * 2][1],
                    bb[0][j2 * 2 + 1][0], bb[0][j2 * 2 + 1][1],
                    bAddr + (j2 * 16 * PITCH) * 2);
        LDSM_X4(aa[0][0], aa[0][1], aa[0][2], aa[0][3], aAddr);

#pragma unroll
        for (int ks = 0; ks < 4; ks++) {
#pragma unroll
            for (int i = 0; i < 4; i++) {
                // prefetch next fragments BEFORE this slot's MMAs (volatile
                // asm keeps this order -> LDSM latency hidden under MMA run)
                if (i < 3) {
                    LDSM_X4(aa[(i + 1) & 1][0], aa[(i + 1) & 1][1],
                            aa[(i + 1) & 1][2], aa[(i + 1) & 1][3],
                            aAddr + ((i + 1) * 16 * PITCH + ks * 16) * 2);
                } else if (ks < 3) {
                    int nb = (ks + 1) & 1;
#pragma unroll
                    for (int j2 = 0; j2 < 4; j2++)
                        LDSM_X4(bb[nb][j2 * 2][0], bb[nb][j2 * 2][1],
                                bb[nb][j2 * 2 + 1][0], bb[nb][j2 * 2 + 1][1],
                                bAddr + (j2 * 16 * PITCH + (ks + 1) * 16) * 2);
                    LDSM_X4(aa[0][0], aa[0][1], aa[0][2], aa[0][3],
                            aAddr + ((ks + 1) * 16) * 2);
                }
#pragma unroll
                for (int j = 0; j < 8; j++)
                    MMA16816(acc[i][j], aa[i & 1], bb[ks & 1][j]);
            }
        }
    }

    // ---------------- epilogue: atomic partial-sum into out ----------------
    int lr = lane >> 2, lc2 = (lane & 3) * 2;
#pragma unroll
    for (int i = 0; i < 4; i++) {
#pragma unroll
        for (int half = 0; half < 2; half++) {
            int o = m0 + wm * 64 + i * 16 + lr + half * 8;
            int cch = o >> 8, p = o & 255, hp = p >> 4, wp = p & 15;
#pragma unroll
            for (int j = 0; j < 8; j++) {
                int s = n0 + wn * 64 + j * 8 + lc2;
                int n = s >> 6, k = (s >> 3) & 7;
                size_t idx = (((size_t)(n * 32 + cch) * 128) + hp * 8 + k) * 128 + wp * 8 + lc2;
                asm volatile("red.global.add.f32 [%0], %1;"
                             :: "l"(out + idx), "f"(acc[i][j][half * 2 + 0]) : "memory");
                asm volatile("red.global.add.f32 [%0], %1;"
                             :: "l"(out + idx + 1), "f"(acc[i][j][half * 2 + 1]) : "memory");
            }
        }
    }
}

// ---------------------------------------------------------------------------
extern "C" void kernel_launch(void* const* d_in, const int* in_sizes, int n_in,
                              void* d_out, int out_size) {
    const float* x = (const float*)d_in[0];   // 8,388,608 elems
    const float* g = (const float*)d_in[1];   // 67,108,864 elems
    if (in_sizes[0] > in_sizes[1]) { const float* tmp = x; x = g; g = tmp; }
    float* out = (float*)d_out;

    cudaFuncSetAttribute(gemm_kernel, cudaFuncAttributeMaxDynamicSharedMemorySize, SMEM_BYTES);
    im2col_kernel<<<8192, 256>>>(x, out);
    gemm_kernel<<<dim3(NDIM / BN, MDIM / BM, KSPLIT), 256, SMEM_BYTES>>>(g, out);
}

// round 14
// speedup vs baseline: 1.0198x; 1.0198x over previous
#include <cuda_runtime.h>
#include <cuda_fp16.h>
#include <cstdint>

// ---------------------------------------------------------------------------
// APUNet as one GEMM: D[o,s] = sum_i G[o,i] * Xs[s,i] ; out = D + x
//   o = c*256 + hp*16 + wp (M=8192), s = n*64 + k*8 + j (N=1024), K=8192
// fp16 mma.sync m16n8k16 — fastest compilable tensor path on this harness
// (tcgen05 rejected by sm_103 PTX target; legacy IMMA measured 4-7x slower;
// tf32 k8 = 2x the HMMA count). BM=128 BN=256 BK=64, warps 2(M)x4(N) 64x64,
// KSPLIT=4 + red.global.add epilogue into out pre-initialized with residual.
// Measured at the legacy HMMA dense-throughput ceiling (~156 TF/s).
// This round: A-loader LDG burst spread across the 4 ks sections (L1tex
// wavefront-queue decollision at chunk boundaries).
// ---------------------------------------------------------------------------

#define MDIM 8192
#define NDIM 1024
#define KDIM 8192
#define BM 128
#define BN 256
#define BK 64
#define KSPLIT 4
#define KGRAN (KDIM / KSPLIT)   // 2048
#define NCHUNK (KGRAN / BK)     // 32
#define PITCH 72                // fp16 units; 144B rows -> ldmatrix conflict-free
#define ASTAGE (BM * PITCH)     // 9216 fp16 (18 KB)
#define BSTAGE (BN * PITCH)     // 18432 fp16 (36 KB)
#define SMEM_BYTES ((2 * ASTAGE + 3 * BSTAGE) * 2)   // 147456

__device__ __half g_Xs[(size_t)NDIM * KDIM];   // 16 MB: im2col(x) in fp16

__device__ __forceinline__ uint32_t smem_u32(const void* p) {
    uint32_t a;
    asm("{ .reg .u64 t; cvta.to.shared.u64 t, %1; cvt.u32.u64 %0, t; }" : "=r"(a) : "l"(p));
    return a;
}
#define LDSM_X4(r0, r1, r2, r3, addr) \
    asm volatile("ldmatrix.sync.aligned.m8n8.x4.shared.b16 {%0,%1,%2,%3}, [%4];" \
                 : "=r"(r0), "=r"(r1), "=r"(r2), "=r"(r3) : "r"(addr))

// ---------------------------------------------------------------------------
// im2col + residual init: Xs[s][i] = fp16(x), out = x  (128-bit IO throughout)
// ---------------------------------------------------------------------------
__global__ void __launch_bounds__(256) im2col_kernel(const float* __restrict__ x,
                                                     float* __restrict__ out) {
    int b = blockIdx.x;                 // (n, c, hp)
    int hp = b & 15, c = (b >> 4) & 31, n = b >> 9;
    __shared__ float tile[1024];        // [k(8)][w(128)]
    size_t base = ((size_t)((n * 32 + c) * 128 + hp * 8)) * 128;
    int t = threadIdx.x;
    {
        float4 v = *(const float4*)(x + base + t * 4);
        *(float4*)(out + base + t * 4) = v;   // residual pre-init
        *(float4*)(tile + t * 4) = v;
    }
    __syncthreads();
    int wp = t & 15;
    int ibase = c * 256 + hp * 16 + wp;
#pragma unroll
    for (int r = 0; r < 4; r++) {
        int sl = (t >> 4) + r * 16;     // 0..63 = k*8+j
        int k = sl >> 3, j = sl & 7;
        g_Xs[(size_t)(n * 64 + sl) * KDIM + ibase] =
            __float2half_rn(tile[k * 128 + wp * 8 + j]);
    }
}

// ---------------------------------------------------------------------------
// GEMM: grid (4 n, 64 m, 4 kq), 256 threads, warps 2(M) x 4(N), tile 64x64
// ---------------------------------------------------------------------------
__global__ void __launch_bounds__(256, 1) gemm_kernel(
    const float* __restrict__ G, float* __restrict__ out) {
    extern __shared__ __half sm[];
    __half* smA = sm;                    // 2 stages (reg double-buffer feed)
    __half* smB = sm + 2 * ASTAGE;       // 3 stages (cp.async)

    int t = threadIdx.x, lane = t & 31, wid = t >> 5;
    int wm = wid >> 2, wn = wid & 3;
    int m0 = blockIdx.y * BM, n0 = blockIdx.x * BN;
    int k0 = blockIdx.z * KGRAN;
    const float* gbase = G + (size_t)m0 * KDIM + k0;
    const __half* bbase = g_Xs + (size_t)n0 * KDIM + k0;

    float acc[4][8][4];
#pragma unroll
    for (int i = 0; i < 4; i++)
#pragma unroll
        for (int j = 0; j < 8; j++)
#pragma unroll
            for (int r = 0; r < 4; r++) acc[i][j][r] = 0.f;

    // ldmatrix base byte-addresses (stage 0, ks 0)
    uint32_t ldsmA = smem_u32(smA) +
        ((wm * 64 + (lane & 15)) * PITCH + (lane >> 4) * 8) * 2;
    uint32_t ldsmB = smem_u32(smB) +
        ((wn * 64 + (lane & 7) + ((lane >> 4) & 1) * 8) * PITCH + ((lane >> 3) & 1) * 8) * 2;

    // A loader: streaming fp32 LDG -> cvt fp16 -> STS.128.
    // LDG split into 4 parts (one per ks section) to avoid the chunk-boundary
    // L1tex wavefront burst.
    float4 areg[4][2];

    auto ldgA_part = [&](int c, int r) {
        int v2 = t + r * 256;
        const float4* src = (const float4*)(gbase + (size_t)(v2 >> 3) * KDIM + c * BK + (v2 & 7) * 8);
        areg[r][0] = __ldcs(src);
        areg[r][1] = __ldcs(src + 1);
    };
    auto ldgA = [&](int c) {
#pragma unroll
        for (int r = 0; r < 4; r++) ldgA_part(c, r);
    };
    auto stsA = [&](int buf) {
#pragma unroll
        for (int r = 0; r < 4; r++) {
            int v2 = t + r * 256;
            __half2 h0 = __floats2half2_rn(areg[r][0].x, areg[r][0].y);
            __half2 h1 = __floats2half2_rn(areg[r][0].z, areg[r][0].w);
            __half2 h2 = __floats2half2_rn(areg[r][1].x, areg[r][1].y);
            __half2 h3 = __floats2half2_rn(areg[r][1].z, areg[r][1].w);
            uint32_t dst = smem_u32(smA + buf * ASTAGE + (v2 >> 3) * PITCH + (v2 & 7) * 8);
            asm volatile("st.shared.v4.b32 [%0], {%1,%2,%3,%4};"
                         :: "r"(dst),
                            "r"(*(uint32_t*)&h0), "r"(*(uint32_t*)&h1),
                            "r"(*(uint32_t*)&h2), "r"(*(uint32_t*)&h3) : "memory");
        }
    };
    auto cpB = [&](int c) {
        __half* base = smB + (c % 3) * BSTAGE;
#pragma unroll
        for (int r = 0; r < 8; r++) {
            int v = t + r * 256;        // 2048: row = v>>3, c4 = v&7
            uint32_t dst = smem_u32(base + (v >> 3) * PITCH + (v & 7) * 8);
            const __half* src = bbase + (size_t)(v >> 3) * KDIM + c * BK + (v & 7) * 8;
            asm volatile("cp.async.cg.shared.global [%0], [%1], 16;" :: "r"(dst), "l"(src) : "memory");
        }
    };

    // prologue
    cpB(0); asm volatile("cp.async.commit_group;" ::: "memory");
    cpB(1); asm volatile("cp.async.commit_group;" ::: "memory");
    ldgA(0); stsA(0);
    ldgA(1);

#pragma unroll 1
    for (int c = 0; c < NCHUNK; c++) {
        asm volatile("cp.async.wait_group 1;" ::: "memory");
        __syncthreads();
        if (c + 2 < NCHUNK) cpB(c + 2);
        asm volatile("cp.async.commit_group;" ::: "memory");
        if (c + 1 < NCHUNK) stsA((c + 1) & 1);

        uint32_t aAddr = ldsmA + (c & 1) * (ASTAGE * 2);
        uint32_t bAddr = ldsmB + (c % 3) * (BSTAGE * 2);
#pragma unroll
        for (int ks = 0; ks < 4; ks++) {          // 4 x k16 per BK=64 chunk
            uint32_t a[4][4], b[8][2];
#pragma unroll
            for (int i = 0; i < 4; i++)
                LDSM_X4(a[i][0], a[i][1], a[i][2], a[i][3],
                        aAddr + (i * 16 * PITCH + ks * 16) * 2);
#pragma unroll
            for (int j2 = 0; j2 < 4; j2++)
                LDSM_X4(b[j2 * 2][0], b[j2 * 2][1], b[j2 * 2 + 1][0], b[j2 * 2 + 1][1],
                        bAddr + (j2 * 16 * PITCH + ks * 16) * 2);
            // spread the next-next chunk's A LDG across the ks sections
            if (c + 2 < NCHUNK) ldgA_part(c + 2, ks);
#pragma unroll
            for (int i = 0; i < 4; i++)
#pragma unroll
                for (int j = 0; j < 8; j++)
                    asm volatile(
                        "mma.sync.aligned.m16n8k16.row.col.f32.f16.f16.f32 "
                        "{%0,%1,%2,%3}, {%4,%5,%6,%7}, {%8,%9}, {%0,%1,%2,%3};"
                        : "+f"(acc[i][j][0]), "+f"(acc[i][j][1]),
                          "+f"(acc[i][j][2]), "+f"(acc[i][j][3])
                        : "r"(a[i][0]), "r"(a[i][1]), "r"(a[i][2]), "r"(a[i][3]),
                          "r"(b[j][0]), "r"(b[j][1]));
        }
    }

    // ---------------- epilogue: atomic partial-sum into out ----------------
    int lr = lane >> 2, lc2 = (lane & 3) * 2;
#pragma unroll
    for (int i = 0; i < 4; i++) {
#pragma unroll
        for (int half = 0; half < 2; half++) {
            int o = m0 + wm * 64 + i * 16 + lr + half * 8;
            int cch = o >> 8, p = o & 255, hp = p >> 4, wp = p & 15;
#pragma unroll
            for (int j = 0; j < 8; j++) {
                int s = n0 + wn * 64 + j * 8 + lc2;
                int n = s >> 6, k = (s >> 3) & 7;
                size_t idx = (((size_t)(n * 32 + cch) * 128) + hp * 8 + k) * 128 + wp * 8 + lc2;
                asm volatile("red.global.add.f32 [%0], %1;"
                             :: "l"(out + idx), "f"(acc[i][j][half * 2 + 0]) : "memory");
                asm volatile("red.global.add.f32 [%0], %1;"
                             :: "l"(out + idx + 1), "f"(acc[i][j][half * 2 + 1]) : "memory");
            }
        }
    }
}

// ---------------------------------------------------------------------------
extern "C" void kernel_launch(void* const* d_in, const int* in_sizes, int n_in,
                              void* d_out, int out_size) {
    const float* x = (const float*)d_in[0];   // 8,388,608 elems
    const float* g = (const float*)d_in[1];   // 67,108,864 elems
    if (in_sizes[0] > in_sizes[1]) { const float* tmp = x; x = g; g = tmp; }
    float* out = (float*)d_out;

    cudaFuncSetAttribute(gemm_kernel, cudaFuncAttributeMaxDynamicSharedMemorySize, SMEM_BYTES);
    im2col_kernel<<<8192, 256>>>(x, out);
    gemm_kernel<<<dim3(NDIM / BN, MDIM / BM, KSPLIT), 256, SMEM_BYTES>>>(g, out);
}